// round 12
// baseline (speedup 1.0000x reference)
#include <cuda_runtime.h>
#include <cuda_bf16.h>
#include <cuda_fp16.h>
#include <mma.h>
#include <math.h>

using namespace nvcuda;

#define NN 100000
#define EE 1600000
#define NF 133
#define HD 128
#define NROWS 100096           // NN rounded up to 128
#define LDA 192                // g_ap row stride in elems (Kpad_max = 192)

typedef unsigned long long ull;
typedef unsigned int u32;

// ---------------- device scratch (static, no runtime alloc) ----------------
__device__ __half g_h[(size_t)NROWS * HD];           // GEMM output (fp16, padded)
__device__ __half g_ap[(size_t)NROWS * LDA];         // A (fp16 activations / input)
__device__ __half g_bp[128 * 192 + 3 * 128 * 128];   // B regions: L0 | L1 | L2 | L3
__device__ float g_dinv[NN];
__device__ int   g_cnt[NN];
__device__ int   g_rowptr[NN];
__device__ int   g_fill[NN];
__device__ int   g_col[EE];
__device__ float g_wgt[EE];
__device__ int   g_bsum[256];
__device__ int   g_is64;

#define B_OFF_L0 0
#define B_OFF_L1 24576
#define B_OFF_L2 40960
#define B_OFF_L3 57344

// ---------------- cp.async helpers ----------------
__device__ __forceinline__ u32 smem_u32(const void* p) {
    u32 a;
    asm("{ .reg .u64 t; cvta.to.shared.u64 t, %1; cvt.u32.u64 %0, t; }" : "=r"(a) : "l"(p));
    return a;
}
__device__ __forceinline__ void cp16(u32 dst, const void* src) {
    asm volatile("cp.async.cg.shared.global [%0], [%1], 16;" :: "r"(dst), "l"(src));
}
__device__ __forceinline__ void cp_commit() {
    asm volatile("cp.async.commit_group;");
}
template <int N>
__device__ __forceinline__ void cp_wait() {
    asm volatile("cp.async.wait_group %0;" :: "n"(N));
}

// ---------------- edge dtype probe ----------------
__global__ void k_probe(const int* __restrict__ ei) {
    __shared__ int nz;
    if (threadIdx.x == 0) nz = 0;
    __syncthreads();
    int v = ei[threadIdx.x * 2 + 1];
    if (v != 0) atomicAdd(&nz, 1);
    __syncthreads();
    if (threadIdx.x == 0) g_is64 = (nz == 0) ? 1 : 0;
}

__device__ __forceinline__ int edge_val(const void* ei, long long idx) {
    if (g_is64) return (int)((const long long*)ei)[idx];
    return ((const int*)ei)[idx];
}

// ---------------- CSR build ----------------
__global__ void k_zero_cnt(int n) {
    int i = blockIdx.x * blockDim.x + threadIdx.x;
    if (i < n) g_cnt[i] = 0;
}

__global__ void k_count(const void* __restrict__ ei, int e) {
    int i = blockIdx.x * blockDim.x + threadIdx.x;
    if (i >= e) return;
    int d = edge_val(ei, (long long)e + i);
    atomicAdd(&g_cnt[d], 1);
}

__global__ void k_scan1(int n) {
    __shared__ int s[1024];
    int t = threadIdx.x;
    int i = blockIdx.x * 1024 + t;
    int v = (i < n) ? g_cnt[i] : 0;
    s[t] = v;
    __syncthreads();
    #pragma unroll
    for (int off = 1; off < 1024; off <<= 1) {
        int x = (t >= off) ? s[t - off] : 0;
        __syncthreads();
        s[t] += x;
        __syncthreads();
    }
    if (i < n) g_rowptr[i] = s[t] - v;
    if (t == 1023) g_bsum[blockIdx.x] = s[1023];
}

__global__ void k_scan2(int nb) {
    if (threadIdx.x == 0) {
        int run = 0;
        for (int b = 0; b < nb; b++) { int t = g_bsum[b]; g_bsum[b] = run; run += t; }
    }
}

__global__ void k_scan3(int n) {
    int i = blockIdx.x * blockDim.x + threadIdx.x;
    if (i >= n) return;
    int r = g_rowptr[i] + g_bsum[i >> 10];
    g_rowptr[i] = r;
    g_fill[i]   = r;
    g_dinv[i]   = rsqrtf((float)g_cnt[i] + 1.0f);
}

__global__ void k_fill(const void* __restrict__ ei, int e) {
    int i = blockIdx.x * blockDim.x + threadIdx.x;
    if (i >= e) return;
    int s = edge_val(ei, i);
    int d = edge_val(ei, (long long)e + i);
    int pos = atomicAdd(&g_fill[d], 1);
    g_col[pos] = s;
    g_wgt[pos] = g_dinv[s] * g_dinv[d];
}

// ---------------- A prep (layer 0 only; later layers fused into k_agg) ------
__global__ void k_prep_a(const float* __restrict__ src, int n, int K, int Kpad, int stride) {
    int total = n * Kpad;
    for (int idx = blockIdx.x * blockDim.x + threadIdx.x; idx < total;
         idx += gridDim.x * blockDim.x) {
        int row = idx / Kpad, c = idx % Kpad;
        float v = (c < K) ? src[(size_t)row * stride + c] : 0.f;
        g_ap[(size_t)row * LDA + c] = __float2half(v);
    }
}

// ---------------- B prep: all 4 layers in one pass --------------------------
// region L0: [128][192] from W0 (K=133, zero-padded); L1-3: [128][128].
__global__ void k_prep_ball(const float* __restrict__ W0, const float* __restrict__ W1,
                            const float* __restrict__ W2, const float* __restrict__ W3) {
    int total = 128 * 192 + 3 * 128 * 128;   // 73728
    for (int idx = blockIdx.x * blockDim.x + threadIdx.x; idx < total;
         idx += gridDim.x * blockDim.x) {
        float w;
        if (idx < B_OFF_L1) {
            int nrow = idx / 192, k = idx % 192;
            w = (k < NF) ? W0[k * HD + nrow] : 0.f;
        } else {
            int r = idx - B_OFF_L1;
            int l = r >> 14;                 // 0..2
            int q = r & 16383;
            int nrow = q >> 7, k = q & 127;
            const float* W = (l == 0) ? W1 : ((l == 1) ? W2 : W3);
            w = W[k * HD + nrow];
        }
        g_bp[idx] = __float2half(w);
    }
}

// ---------------- WMMA GEMM: C[n,128] = A[n,K] @ B[K,128], fp16 acc/out -----
// Grid (mblocks, 2): output tile 128x64 per CTA, 8 warps, warp tile 32x32.
// A tile resident in smem; B (this CTA's 64 n-rows) streamed in 64-k slabs
// via 3-deep cp.async ring. fp16 accumulators; DIRECT fp16 global store.
#define BSLAB_LD 72                        // elems per B slab row (64 + 8 pad)
#define BSLAB_ROWS 64
#define BSLAB_BYTES (BSLAB_ROWS * BSLAB_LD * 2)   // 9216
__global__ __launch_bounds__(256, 3) void k_wgemm(const __half* __restrict__ Ap,
                                                  __half* __restrict__ C,
                                                  int Kpad, int nbslab, int ldaS, int bOff) {
    extern __shared__ char smem[];
    char* aBase = smem;                                  // 128 * ldaS * 2 bytes
    char* bBase = smem + 128 * ldaS * 2;                 // 3 x BSLAB_BYTES
    u32 aBaseU = smem_u32(aBase);
    u32 bBaseU = smem_u32(bBase);
    int K2 = nbslab * 64;
    int tid = threadIdx.x, wid = tid >> 5;
    int row0 = blockIdx.x * 128;
    int ncol0 = blockIdx.y * 64;                         // N-split
    int mrow = (wid & 3) * 32;
    int ncw  = (wid >> 2) * 32;
    const __half* bp = g_bp + bOff;

    // ---- stage full A tile + B slab 0 (one cp.async group) ----
    {
        int vpr = Kpad >> 3;                 // 16B vectors per A row
        int nAv = 128 * vpr;
        for (int q = tid; q < nAv; q += 256) {
            int row = q / vpr, part = q - row * vpr;
            cp16(aBaseU + (u32)(row * ldaS * 2 + part * 16),
                 Ap + (size_t)(row0 + row) * LDA + part * 8);
        }
        for (int q = tid; q < 512; q += 256) {
            int row = q >> 3, part = q & 7;
            cp16(bBaseU + (u32)(row * (BSLAB_LD * 2) + part * 16),
                 bp + (size_t)(ncol0 + row) * K2 + part * 8);
        }
    }
    cp_commit();

    wmma::fragment<wmma::accumulator, 16, 16, 16, __half> acc[2][2];
    #pragma unroll
    for (int i = 0; i < 2; i++)
        #pragma unroll
        for (int j = 0; j < 2; j++) wmma::fill_fragment(acc[i][j], __float2half(0.f));

    int slot = 0, nslot = 1;
    for (int s = 0; s < nbslab; s++) {
        if (s + 1 < nbslab) {
            int kp = (s + 1) * 64;
            u32 bbuf = bBaseU + (u32)(nslot * BSLAB_BYTES);
            for (int q = tid; q < 512; q += 256) {
                int row = q >> 3, part = q & 7;
                cp16(bbuf + (u32)(row * (BSLAB_LD * 2) + part * 16),
                     bp + (size_t)(ncol0 + row) * K2 + kp + part * 8);
            }
            cp_commit();
            cp_wait<1>();
        } else {
            cp_wait<0>();
        }
        __syncthreads();                    // slab s visible; iter s-2 reads done

        const __half* aSm   = (const __half*)aBase;
        const __half* bSlab = (const __half*)(bBase + slot * BSLAB_BYTES);
        #pragma unroll
        for (int half = 0; half < 4; half++) {
            int kp = s * 64 + half * 16;
            wmma::fragment<wmma::matrix_a, 16, 16, 16, __half, wmma::row_major> af[2];
            #pragma unroll
            for (int i = 0; i < 2; i++)
                wmma::load_matrix_sync(af[i], aSm + (mrow + i * 16) * ldaS + kp, ldaS);
            wmma::fragment<wmma::matrix_b, 16, 16, 16, __half, wmma::col_major> bfr[2];
            #pragma unroll
            for (int j = 0; j < 2; j++)
                wmma::load_matrix_sync(bfr[j], bSlab + (ncw + j * 16) * BSLAB_LD + half * 16, BSLAB_LD);
            #pragma unroll
            for (int i = 0; i < 2; i++)
                #pragma unroll
                for (int j = 0; j < 2; j++)
                    wmma::mma_sync(acc[i][j], af[i], bfr[j], acc[i][j]);
        }
        slot = nslot;
        nslot = (nslot + 1 == 3) ? 0 : nslot + 1;
    }

    // ---- epilogue: direct fp16 store (rows padded to NROWS; all tiles full) ----
    #pragma unroll
    for (int i = 0; i < 2; i++)
        #pragma unroll
        for (int j = 0; j < 2; j++)
            wmma::store_matrix_sync(C + (size_t)(row0 + mrow + i * 16) * HD + ncol0 + ncw + j * 16,
                                    acc[i][j], HD, wmma::mem_row_major);
}

// ---------------- Aggregation: half-warp per node, uint4 gathers ------------
// h is fp16 (256B/row = 16 lanes x 16B). mode 0: emit fp16 to g_ap. 1: fp32 out.
__global__ __launch_bounds__(256) void k_agg(const __half* __restrict__ h,
                                             const float* __restrict__ bias,
                                             float* __restrict__ out, int n, int mode) {
    int t  = blockIdx.x * blockDim.x + threadIdx.x;
    int nd = t >> 4;              // node (half-warp)
    int hl = t & 15;              // lane within half-warp; owns 8 cols
    if (nd >= n) return;
    int start = g_rowptr[nd];
    int cnt   = g_cnt[nd];
    int c0 = hl * 8;

    float acc[8] = {0.f, 0.f, 0.f, 0.f, 0.f, 0.f, 0.f, 0.f};
    for (int e = 0; e < cnt; e++) {
        int idx  = start + e;
        int s    = g_col[idx];
        float we = g_wgt[idx];
        union { __half2 h2[4]; uint4 u; } hv;
        hv.u = *(const uint4*)(h + (size_t)s * HD + c0);
        #pragma unroll
        for (int k = 0; k < 4; k++) {
            float2 f = __half22float2(hv.h2[k]);
            acc[2 * k]     += we * f.x;
            acc[2 * k + 1] += we * f.y;
        }
    }
    float di = g_dinv[nd];
    float d2 = di * di;
    union { __half2 h2[4]; uint4 u; } hs;
    hs.u = *(const uint4*)(h + (size_t)nd * HD + c0);
    float4 bv0 = *(const float4*)&bias[c0];
    float4 bv1 = *(const float4*)&bias[c0 + 4];
    float bb[8] = {bv0.x, bv0.y, bv0.z, bv0.w, bv1.x, bv1.y, bv1.z, bv1.w};
    #pragma unroll
    for (int k = 0; k < 4; k++) {
        float2 f = __half22float2(hs.h2[k]);
        acc[2 * k]     = tanhf(acc[2 * k]     + d2 * f.x + bb[2 * k]);
        acc[2 * k + 1] = tanhf(acc[2 * k + 1] + d2 * f.y + bb[2 * k + 1]);
    }

    if (mode == 1) {
        float4 o0 = make_float4(acc[0], acc[1], acc[2], acc[3]);
        float4 o1 = make_float4(acc[4], acc[5], acc[6], acc[7]);
        *(float4*)&out[(size_t)nd * HD + c0]     = o0;
        *(float4*)&out[(size_t)nd * HD + c0 + 4] = o1;
    } else {
        union { __half2 h2[4]; uint4 u; } o;
        #pragma unroll
        for (int k = 0; k < 4; k++)
            o.h2[k] = __floats2half2_rn(acc[2 * k], acc[2 * k + 1]);
        *(uint4*)&g_ap[(size_t)nd * LDA + c0] = o.u;
    }
}

// ---------------- launch ----------------
extern "C" void kernel_launch(void* const* d_in, const int* in_sizes, int n_in,
                              void* d_out, int out_size) {
    const float* x  = (const float*)d_in[0];
    const void*  ei = d_in[1];
    const float* W0 = (const float*)d_in[2];
    const float* b0 = (const float*)d_in[3];
    const float* W1 = (const float*)d_in[4];
    const float* b1 = (const float*)d_in[5];
    const float* W2 = (const float*)d_in[6];
    const float* b2 = (const float*)d_in[7];
    const float* W3 = (const float*)d_in[8];
    const float* b3 = (const float*)d_in[9];
    float* out = (float*)d_out;

    int n  = in_sizes[0] / NF;   // 100000
    int e  = in_sizes[1] / 2;    // 1600000
    int nb = (n + 1023) / 1024;

    __half *hbuf, *apf;
    cudaGetSymbolAddress((void**)&hbuf, g_h);
    cudaGetSymbolAddress((void**)&apf, g_ap);
    const __half* ap = (const __half*)apf;

    // smem: L0 = 128*200*2 + 3*9216 = 78848 ; L1-3 = 128*136*2 + 3*9216 = 62464
    cudaFuncSetAttribute(k_wgemm, cudaFuncAttributeMaxDynamicSharedMemorySize, 78848);

    dim3 ggrid((n + 127) / 128, 2);             // (782, 2)
    int agg_blocks = (n * 16 + 255) / 256;      // 6250

    // layer-0 GEMM first (independent of CSR) so ncu -s lands on k_wgemm
    k_probe<<<1, 256>>>((const int*)ei);                              // 0
    k_prep_a<<<1024, 256>>>(x, n, NF, 192, NF);                       // 1
    k_prep_ball<<<288, 256>>>(W0, W1, W2, W3);                        // 2
    k_wgemm<<<ggrid, 256, 78848>>>(ap, hbuf, 192, 3, 200, B_OFF_L0);  // 3
    // CSR build
    k_zero_cnt<<<(n + 255) / 256, 256>>>(n);
    k_count<<<(e + 255) / 256, 256>>>(ei, e);
    k_scan1<<<nb, 1024>>>(n);
    k_scan2<<<1, 32>>>(nb);
    k_scan3<<<(n + 255) / 256, 256>>>(n);
    k_fill<<<(e + 255) / 256, 256>>>(ei, e);
    // layer 0 aggregate, then layers 1-3
    k_agg<<<agg_blocks, 256>>>(hbuf, b0, out, n, 0);
    k_wgemm<<<ggrid, 256, 62464>>>(ap, hbuf, HD, 2, 136, B_OFF_L1);
    k_agg<<<agg_blocks, 256>>>(hbuf, b1, out, n, 0);
    k_wgemm<<<ggrid, 256, 62464>>>(ap, hbuf, HD, 2, 136, B_OFF_L2);
    k_agg<<<agg_blocks, 256>>>(hbuf, b2, out, n, 0);
    k_wgemm<<<ggrid, 256, 62464>>>(ap, hbuf, HD, 2, 136, B_OFF_L3);
    k_agg<<<agg_blocks, 256>>>(hbuf, b3, out, n, 1);
}

// round 13
// speedup vs baseline: 1.0643x; 1.0643x over previous
#include <cuda_runtime.h>
#include <cuda_bf16.h>
#include <cuda_fp16.h>
#include <mma.h>
#include <math.h>

using namespace nvcuda;

#define NN 100000
#define EE 1600000
#define NF 133
#define HD 128
#define NROWS 100096           // NN rounded up to 128
#define LDA 192                // g_ap row stride in elems (Kpad_max = 192)

typedef unsigned long long ull;
typedef unsigned int u32;

// ---------------- device scratch (static, no runtime alloc) ----------------
__device__ __half g_h[(size_t)NROWS * HD];           // GEMM output (fp16, padded)
__device__ __half g_ap[(size_t)NROWS * LDA];         // A (fp16 activations / input)
__device__ __half g_bp[128 * 192 + 3 * 128 * 128];   // B regions: L0 | L1 | L2 | L3
__device__ float g_dinv[NN];
__device__ int   g_cnt[NN];
__device__ int   g_rowptr[NN];
__device__ int   g_fill[NN];
__device__ int   g_col[EE];
__device__ float g_wgt[EE];
__device__ int   g_bsum[256];
__device__ int   g_is64;

#define B_OFF_L0 0
#define B_OFF_L1 24576
#define B_OFF_L2 40960
#define B_OFF_L3 57344

// ---------------- cp.async helpers ----------------
__device__ __forceinline__ u32 smem_u32(const void* p) {
    u32 a;
    asm("{ .reg .u64 t; cvta.to.shared.u64 t, %1; cvt.u32.u64 %0, t; }" : "=r"(a) : "l"(p));
    return a;
}
__device__ __forceinline__ void cp16(u32 dst, const void* src) {
    asm volatile("cp.async.cg.shared.global [%0], [%1], 16;" :: "r"(dst), "l"(src));
}
__device__ __forceinline__ void cp_commit() {
    asm volatile("cp.async.commit_group;");
}
template <int N>
__device__ __forceinline__ void cp_wait() {
    asm volatile("cp.async.wait_group %0;" :: "n"(N));
}

// ---------------- probe + zero counters (merged) ----------------
__global__ void k_probe_zero(const int* __restrict__ ei, int n) {
    int i = blockIdx.x * blockDim.x + threadIdx.x;
    if (blockIdx.x == 0) {
        __shared__ int nz;
        if (threadIdx.x == 0) nz = 0;
        __syncthreads();
        int v = ei[threadIdx.x * 2 + 1];
        if (v != 0) atomicAdd(&nz, 1);
        __syncthreads();
        if (threadIdx.x == 0) g_is64 = (nz == 0) ? 1 : 0;
    }
    if (i < n) g_cnt[i] = 0;
}

__device__ __forceinline__ int edge_val(const void* ei, long long idx) {
    if (g_is64) return (int)((const long long*)ei)[idx];
    return ((const int*)ei)[idx];
}

// ---------------- CSR build ----------------
__global__ void k_count(const void* __restrict__ ei, int e) {
    int i = blockIdx.x * blockDim.x + threadIdx.x;
    if (i >= e) return;
    int d = edge_val(ei, (long long)e + i);
    atomicAdd(&g_cnt[d], 1);
}

__global__ void k_scan1(int n) {
    __shared__ int s[1024];
    int t = threadIdx.x;
    int i = blockIdx.x * 1024 + t;
    int v = (i < n) ? g_cnt[i] : 0;
    s[t] = v;
    __syncthreads();
    #pragma unroll
    for (int off = 1; off < 1024; off <<= 1) {
        int x = (t >= off) ? s[t - off] : 0;
        __syncthreads();
        s[t] += x;
        __syncthreads();
    }
    if (i < n) g_rowptr[i] = s[t] - v;
    if (t == 1023) g_bsum[blockIdx.x] = s[1023];
}

__global__ void k_scan2(int nb) {
    if (threadIdx.x == 0) {
        int run = 0;
        for (int b = 0; b < nb; b++) { int t = g_bsum[b]; g_bsum[b] = run; run += t; }
    }
}

__global__ void k_scan3(int n) {
    int i = blockIdx.x * blockDim.x + threadIdx.x;
    if (i >= n) return;
    int r = g_rowptr[i] + g_bsum[i >> 10];
    g_rowptr[i] = r;
    g_fill[i]   = r;
    g_dinv[i]   = rsqrtf((float)g_cnt[i] + 1.0f);
}

__global__ void k_fill(const void* __restrict__ ei, int e) {
    int i = blockIdx.x * blockDim.x + threadIdx.x;
    if (i >= e) return;
    int s = edge_val(ei, i);
    int d = edge_val(ei, (long long)e + i);
    int pos = atomicAdd(&g_fill[d], 1);
    g_col[pos] = s;
    g_wgt[pos] = g_dinv[s] * g_dinv[d];
}

// ---------------- A prep (layer 0 only; later layers fused into k_agg) ------
__global__ void k_prep_a(const float* __restrict__ src, int n, int K, int Kpad, int stride) {
    int total = n * Kpad;
    for (int idx = blockIdx.x * blockDim.x + threadIdx.x; idx < total;
         idx += gridDim.x * blockDim.x) {
        int row = idx / Kpad, c = idx % Kpad;
        float v = (c < K) ? src[(size_t)row * stride + c] : 0.f;
        g_ap[(size_t)row * LDA + c] = __float2half(v);
    }
}

// ---------------- B prep: all 4 layers in one pass --------------------------
__global__ void k_prep_ball(const float* __restrict__ W0, const float* __restrict__ W1,
                            const float* __restrict__ W2, const float* __restrict__ W3) {
    int total = 128 * 192 + 3 * 128 * 128;   // 73728
    for (int idx = blockIdx.x * blockDim.x + threadIdx.x; idx < total;
         idx += gridDim.x * blockDim.x) {
        float w;
        if (idx < B_OFF_L1) {
            int nrow = idx / 192, k = idx % 192;
            w = (k < NF) ? W0[k * HD + nrow] : 0.f;
        } else {
            int r = idx - B_OFF_L1;
            int l = r >> 14;                 // 0..2
            int q = r & 16383;
            int nrow = q >> 7, k = q & 127;
            const float* W = (l == 0) ? W1 : ((l == 1) ? W2 : W3);
            w = W[k * HD + nrow];
        }
        g_bp[idx] = __float2half(w);
    }
}

// ---------------- WMMA GEMM: C[n,128] = A[n,K] @ B[K,128], fp16 acc/out -----
#define BSLAB_LD 72                        // elems per B slab row (64 + 8 pad)
#define BSLAB_ROWS 64
#define BSLAB_BYTES (BSLAB_ROWS * BSLAB_LD * 2)   // 9216
__global__ __launch_bounds__(256, 3) void k_wgemm(const __half* __restrict__ Ap,
                                                  __half* __restrict__ C,
                                                  int Kpad, int nbslab, int ldaS, int bOff) {
    extern __shared__ char smem[];
    char* aBase = smem;                                  // 128 * ldaS * 2 bytes
    char* bBase = smem + 128 * ldaS * 2;                 // 3 x BSLAB_BYTES
    u32 aBaseU = smem_u32(aBase);
    u32 bBaseU = smem_u32(bBase);
    int K2 = nbslab * 64;
    int tid = threadIdx.x, wid = tid >> 5;
    int row0 = blockIdx.x * 128;
    int ncol0 = blockIdx.y * 64;                         // N-split
    int mrow = (wid & 3) * 32;
    int ncw  = (wid >> 2) * 32;
    const __half* bp = g_bp + bOff;

    // ---- stage full A tile + B slab 0 (one cp.async group) ----
    {
        int vpr = Kpad >> 3;                 // 16B vectors per A row
        int nAv = 128 * vpr;
        for (int q = tid; q < nAv; q += 256) {
            int row = q / vpr, part = q - row * vpr;
            cp16(aBaseU + (u32)(row * ldaS * 2 + part * 16),
                 Ap + (size_t)(row0 + row) * LDA + part * 8);
        }
        for (int q = tid; q < 512; q += 256) {
            int row = q >> 3, part = q & 7;
            cp16(bBaseU + (u32)(row * (BSLAB_LD * 2) + part * 16),
                 bp + (size_t)(ncol0 + row) * K2 + part * 8);
        }
    }
    cp_commit();

    wmma::fragment<wmma::accumulator, 16, 16, 16, __half> acc[2][2];
    #pragma unroll
    for (int i = 0; i < 2; i++)
        #pragma unroll
        for (int j = 0; j < 2; j++) wmma::fill_fragment(acc[i][j], __float2half(0.f));

    int slot = 0, nslot = 1;
    for (int s = 0; s < nbslab; s++) {
        if (s + 1 < nbslab) {
            int kp = (s + 1) * 64;
            u32 bbuf = bBaseU + (u32)(nslot * BSLAB_BYTES);
            for (int q = tid; q < 512; q += 256) {
                int row = q >> 3, part = q & 7;
                cp16(bbuf + (u32)(row * (BSLAB_LD * 2) + part * 16),
                     bp + (size_t)(ncol0 + row) * K2 + kp + part * 8);
            }
            cp_commit();
            cp_wait<1>();
        } else {
            cp_wait<0>();
        }
        __syncthreads();                    // slab s visible; iter s-2 reads done

        const __half* aSm   = (const __half*)aBase;
        const __half* bSlab = (const __half*)(bBase + slot * BSLAB_BYTES);
        #pragma unroll
        for (int half = 0; half < 4; half++) {
            int kp = s * 64 + half * 16;
            wmma::fragment<wmma::matrix_a, 16, 16, 16, __half, wmma::row_major> af[2];
            #pragma unroll
            for (int i = 0; i < 2; i++)
                wmma::load_matrix_sync(af[i], aSm + (mrow + i * 16) * ldaS + kp, ldaS);
            wmma::fragment<wmma::matrix_b, 16, 16, 16, __half, wmma::col_major> bfr[2];
            #pragma unroll
            for (int j = 0; j < 2; j++)
                wmma::load_matrix_sync(bfr[j], bSlab + (ncw + j * 16) * BSLAB_LD + half * 16, BSLAB_LD);
            #pragma unroll
            for (int i = 0; i < 2; i++)
                #pragma unroll
                for (int j = 0; j < 2; j++)
                    wmma::mma_sync(acc[i][j], af[i], bfr[j], acc[i][j]);
        }
        slot = nslot;
        nslot = (nslot + 1 == 3) ? 0 : nslot + 1;
    }

    // ---- epilogue: direct fp16 store (rows padded to NROWS; all tiles full) ----
    #pragma unroll
    for (int i = 0; i < 2; i++)
        #pragma unroll
        for (int j = 0; j < 2; j++)
            wmma::store_matrix_sync(C + (size_t)(row0 + mrow + i * 16) * HD + ncol0 + ncw + j * 16,
                                    acc[i][j], HD, wmma::mem_row_major);
}

// ---------------- Aggregation: half-warp per node, uint4 gathers ------------
__global__ __launch_bounds__(256) void k_agg(const __half* __restrict__ h,
                                             const float* __restrict__ bias,
                                             float* __restrict__ out, int n, int mode) {
    int t  = blockIdx.x * blockDim.x + threadIdx.x;
    int nd = t >> 4;              // node (half-warp)
    int hl = t & 15;              // lane within half-warp; owns 8 cols
    if (nd >= n) return;
    int start = g_rowptr[nd];
    int cnt   = g_cnt[nd];
    int c0 = hl * 8;

    float acc[8] = {0.f, 0.f, 0.f, 0.f, 0.f, 0.f, 0.f, 0.f};
    for (int e = 0; e < cnt; e++) {
        int idx  = start + e;
        int s    = g_col[idx];
        float we = g_wgt[idx];
        union { __half2 h2[4]; uint4 u; } hv;
        hv.u = *(const uint4*)(h + (size_t)s * HD + c0);
        #pragma unroll
        for (int k = 0; k < 4; k++) {
            float2 f = __half22float2(hv.h2[k]);
            acc[2 * k]     += we * f.x;
            acc[2 * k + 1] += we * f.y;
        }
    }
    float di = g_dinv[nd];
    float d2 = di * di;
    union { __half2 h2[4]; uint4 u; } hs;
    hs.u = *(const uint4*)(h + (size_t)nd * HD + c0);
    float4 bv0 = *(const float4*)&bias[c0];
    float4 bv1 = *(const float4*)&bias[c0 + 4];
    float bb[8] = {bv0.x, bv0.y, bv0.z, bv0.w, bv1.x, bv1.y, bv1.z, bv1.w};
    #pragma unroll
    for (int k = 0; k < 4; k++) {
        float2 f = __half22float2(hs.h2[k]);
        acc[2 * k]     = tanhf(acc[2 * k]     + d2 * f.x + bb[2 * k]);
        acc[2 * k + 1] = tanhf(acc[2 * k + 1] + d2 * f.y + bb[2 * k + 1]);
    }

    if (mode == 1) {
        float4 o0 = make_float4(acc[0], acc[1], acc[2], acc[3]);
        float4 o1 = make_float4(acc[4], acc[5], acc[6], acc[7]);
        *(float4*)&out[(size_t)nd * HD + c0]     = o0;
        *(float4*)&out[(size_t)nd * HD + c0 + 4] = o1;
    } else {
        union { __half2 h2[4]; uint4 u; } o;
        #pragma unroll
        for (int k = 0; k < 4; k++)
            o.h2[k] = __floats2half2_rn(acc[2 * k], acc[2 * k + 1]);
        *(uint4*)&g_ap[(size_t)nd * LDA + c0] = o.u;
    }
}

// ---------------- launch ----------------
extern "C" void kernel_launch(void* const* d_in, const int* in_sizes, int n_in,
                              void* d_out, int out_size) {
    const float* x  = (const float*)d_in[0];
    const void*  ei = d_in[1];
    const float* W0 = (const float*)d_in[2];
    const float* b0 = (const float*)d_in[3];
    const float* W1 = (const float*)d_in[4];
    const float* b1 = (const float*)d_in[5];
    const float* W2 = (const float*)d_in[6];
    const float* b2 = (const float*)d_in[7];
    const float* W3 = (const float*)d_in[8];
    const float* b3 = (const float*)d_in[9];
    float* out = (float*)d_out;

    int n  = in_sizes[0] / NF;   // 100000
    int e  = in_sizes[1] / 2;    // 1600000
    int nb = (n + 1023) / 1024;

    __half *hbuf, *apf;
    cudaGetSymbolAddress((void**)&hbuf, g_h);
    cudaGetSymbolAddress((void**)&apf, g_ap);
    const __half* ap = (const __half*)apf;

    cudaFuncSetAttribute(k_wgemm, cudaFuncAttributeMaxDynamicSharedMemorySize, 78848);

    dim3 ggrid((n + 127) / 128, 2);             // (782, 2)
    int agg_blocks = (n * 16 + 255) / 256;      // 6250

    // ---- capture fork: CSR chain on s2 runs concurrently with prep+GEMM L0 ----
    cudaStream_t s2;
    cudaStreamCreateWithFlags(&s2, cudaStreamNonBlocking);
    cudaEvent_t e1, e2;
    cudaEventCreateWithFlags(&e1, cudaEventDisableTiming);
    cudaEventCreateWithFlags(&e2, cudaEventDisableTiming);

    // root: probe + zero counters (both branches depend on this)
    k_probe_zero<<<(n + 255) / 256, 256>>>((const int*)ei, n);
    cudaEventRecord(e1, 0);
    cudaStreamWaitEvent(s2, e1, 0);

    // branch A (default stream): preps + layer-0 GEMM
    k_prep_a<<<1024, 256>>>(x, n, NF, 192, NF);
    k_prep_ball<<<288, 256>>>(W0, W1, W2, W3);
    k_wgemm<<<ggrid, 256, 78848>>>(ap, hbuf, 192, 3, 200, B_OFF_L0);

    // branch B (s2): CSR build
    k_count<<<(e + 255) / 256, 256, 0, s2>>>(ei, e);
    k_scan1<<<nb, 1024, 0, s2>>>(n);
    k_scan2<<<1, 32, 0, s2>>>(nb);
    k_scan3<<<(n + 255) / 256, 256, 0, s2>>>(n);
    k_fill<<<(e + 255) / 256, 256, 0, s2>>>(ei, e);
    cudaEventRecord(e2, s2);
    cudaStreamWaitEvent(0, e2, 0);

    // join: layer 0 aggregate, then layers 1-3 (serial dependence)
    k_agg<<<agg_blocks, 256>>>(hbuf, b0, out, n, 0);
    k_wgemm<<<ggrid, 256, 62464>>>(ap, hbuf, HD, 2, 136, B_OFF_L1);
    k_agg<<<agg_blocks, 256>>>(hbuf, b1, out, n, 0);
    k_wgemm<<<ggrid, 256, 62464>>>(ap, hbuf, HD, 2, 136, B_OFF_L2);
    k_agg<<<agg_blocks, 256>>>(hbuf, b2, out, n, 0);
    k_wgemm<<<ggrid, 256, 62464>>>(ap, hbuf, HD, 2, 136, B_OFF_L3);
    k_agg<<<agg_blocks, 256>>>(hbuf, b3, out, n, 1);
}

// round 14
// speedup vs baseline: 1.0973x; 1.0310x over previous
#include <cuda_runtime.h>
#include <cuda_bf16.h>
#include <cuda_fp16.h>
#include <mma.h>
#include <math.h>

using namespace nvcuda;

#define NN 100000
#define EE 1600000
#define NF 133
#define HD 128
#define NROWS 100096           // NN rounded up to 128
#define LDA 192                // g_ap row stride in elems (Kpad_max = 192)

typedef unsigned long long ull;
typedef unsigned int u32;

// ---------------- device scratch (static, no runtime alloc) ----------------
__device__ __half g_h[(size_t)NROWS * HD];           // GEMM output (fp16, padded)
__device__ __half g_ap[(size_t)NROWS * LDA];         // A (fp16 activations / input)
__device__ __half g_bp[128 * 192 + 3 * 128 * 128];   // B regions: L0 | L1 | L2 | L3
__device__ float g_dinv[NN];
__device__ int   g_cnt[NN];
__device__ int   g_rowptr[NN];
__device__ int   g_fill[NN];
__device__ int   g_col[EE];
__device__ float g_wgt[EE];
__device__ int   g_bsum[256];
__device__ int   g_is64;

#define B_OFF_L0 0
#define B_OFF_L1 24576
#define B_OFF_L2 40960
#define B_OFF_L3 57344

// ---------------- cp.async helpers ----------------
__device__ __forceinline__ u32 smem_u32(const void* p) {
    u32 a;
    asm("{ .reg .u64 t; cvta.to.shared.u64 t, %1; cvt.u32.u64 %0, t; }" : "=r"(a) : "l"(p));
    return a;
}
__device__ __forceinline__ void cp16(u32 dst, const void* src) {
    asm volatile("cp.async.cg.shared.global [%0], [%1], 16;" :: "r"(dst), "l"(src));
}
__device__ __forceinline__ void cp_commit() {
    asm volatile("cp.async.commit_group;");
}
template <int N>
__device__ __forceinline__ void cp_wait() {
    asm volatile("cp.async.wait_group %0;" :: "n"(N));
}

// ---------------- probe + zero counters (merged) ----------------
__global__ void k_probe_zero(const int* __restrict__ ei, int n) {
    int i = blockIdx.x * blockDim.x + threadIdx.x;
    if (blockIdx.x == 0) {
        __shared__ int nz;
        if (threadIdx.x == 0) nz = 0;
        __syncthreads();
        int v = ei[threadIdx.x * 2 + 1];
        if (v != 0) atomicAdd(&nz, 1);
        __syncthreads();
        if (threadIdx.x == 0) g_is64 = (nz == 0) ? 1 : 0;
    }
    if (i < n) g_cnt[i] = 0;
}

__device__ __forceinline__ int edge_val(const void* ei, long long idx) {
    if (g_is64) return (int)((const long long*)ei)[idx];
    return ((const int*)ei)[idx];
}

// ---------------- CSR build ----------------
__global__ void k_count(const void* __restrict__ ei, int e) {
    int i = blockIdx.x * blockDim.x + threadIdx.x;
    if (i >= e) return;
    int d = edge_val(ei, (long long)e + i);
    atomicAdd(&g_cnt[d], 1);
}

__global__ void k_scan1(int n) {
    __shared__ int s[1024];
    int t = threadIdx.x;
    int i = blockIdx.x * 1024 + t;
    int v = (i < n) ? g_cnt[i] : 0;
    s[t] = v;
    __syncthreads();
    #pragma unroll
    for (int off = 1; off < 1024; off <<= 1) {
        int x = (t >= off) ? s[t - off] : 0;
        __syncthreads();
        s[t] += x;
        __syncthreads();
    }
    if (i < n) g_rowptr[i] = s[t] - v;
    if (t == 1023) g_bsum[blockIdx.x] = s[1023];
}

__global__ void k_scan2(int nb) {
    if (threadIdx.x == 0) {
        int run = 0;
        for (int b = 0; b < nb; b++) { int t = g_bsum[b]; g_bsum[b] = run; run += t; }
    }
}

__global__ void k_scan3(int n) {
    int i = blockIdx.x * blockDim.x + threadIdx.x;
    if (i >= n) return;
    int r = g_rowptr[i] + g_bsum[i >> 10];
    g_rowptr[i] = r;
    g_fill[i]   = r;
    g_dinv[i]   = rsqrtf((float)g_cnt[i] + 1.0f);
}

__global__ void k_fill(const void* __restrict__ ei, int e) {
    int i = blockIdx.x * blockDim.x + threadIdx.x;
    if (i >= e) return;
    int s = edge_val(ei, i);
    int d = edge_val(ei, (long long)e + i);
    int pos = atomicAdd(&g_fill[d], 1);
    g_col[pos] = s;
    g_wgt[pos] = g_dinv[s] * g_dinv[d];
}

// ---------------- A prep (layer 0 only; later layers fused into k_agg) ------
__global__ void k_prep_a(const float* __restrict__ src, int n, int K, int Kpad, int stride) {
    int total = n * Kpad;
    for (int idx = blockIdx.x * blockDim.x + threadIdx.x; idx < total;
         idx += gridDim.x * blockDim.x) {
        int row = idx / Kpad, c = idx % Kpad;
        float v = (c < K) ? src[(size_t)row * stride + c] : 0.f;
        g_ap[(size_t)row * LDA + c] = __float2half(v);
    }
}

// ---------------- B prep: all 4 layers in one pass --------------------------
__global__ void k_prep_ball(const float* __restrict__ W0, const float* __restrict__ W1,
                            const float* __restrict__ W2, const float* __restrict__ W3) {
    int total = 128 * 192 + 3 * 128 * 128;   // 73728
    for (int idx = blockIdx.x * blockDim.x + threadIdx.x; idx < total;
         idx += gridDim.x * blockDim.x) {
        float w;
        if (idx < B_OFF_L1) {
            int nrow = idx / 192, k = idx % 192;
            w = (k < NF) ? W0[k * HD + nrow] : 0.f;
        } else {
            int r = idx - B_OFF_L1;
            int l = r >> 14;                 // 0..2
            int q = r & 16383;
            int nrow = q >> 7, k = q & 127;
            const float* W = (l == 0) ? W1 : ((l == 1) ? W2 : W3);
            w = W[k * HD + nrow];
        }
        g_bp[idx] = __float2half(w);
    }
}

// ---------------- WMMA GEMM: C[n,128] = A[n,K] @ B[K,128], fp16 acc/out -----
// Grid (782): output tile 128x128 per CTA, 8 warps, warp tile 32x64.
// A tile AND full B matrix staged to smem in ONE cp.async group ->
// one wait + one barrier total, then straight MMA k-steps, direct store.
__global__ __launch_bounds__(256, 3) void k_wgemm(const __half* __restrict__ Ap,
                                                  __half* __restrict__ C,
                                                  int Kpad, int ldS, int bOff) {
    extern __shared__ char smem[];
    char* aBase = smem;                                  // 128 * ldS * 2
    char* bBase = smem + 128 * ldS * 2;                  // 128 * ldS * 2
    u32 aBaseU = smem_u32(aBase);
    u32 bBaseU = smem_u32(bBase);
    int tid = threadIdx.x, wid = tid >> 5;
    int row0 = blockIdx.x * 128;
    int mrow = (wid & 3) * 32;
    int ncw  = (wid >> 2) * 64;
    const __half* bp = g_bp + bOff;

    // ---- stage A tile + full B (one cp.async group) ----
    {
        int vpr = Kpad >> 3;                 // 16B vectors per row
        int nv = 128 * vpr;
        for (int q = tid; q < nv; q += 256) {
            int row = q / vpr, part = q - row * vpr;
            cp16(aBaseU + (u32)(row * ldS * 2 + part * 16),
                 Ap + (size_t)(row0 + row) * LDA + part * 8);
            cp16(bBaseU + (u32)(row * ldS * 2 + part * 16),
                 bp + (size_t)row * Kpad + part * 8);
        }
    }
    cp_commit();

    wmma::fragment<wmma::accumulator, 16, 16, 16, __half> acc[2][4];
    #pragma unroll
    for (int i = 0; i < 2; i++)
        #pragma unroll
        for (int j = 0; j < 4; j++) wmma::fill_fragment(acc[i][j], __float2half(0.f));

    cp_wait<0>();
    __syncthreads();                         // the ONLY barrier

    const __half* aSm = (const __half*)aBase;
    const __half* bSm = (const __half*)bBase;
    for (int kk = 0; kk < Kpad; kk += 16) {
        wmma::fragment<wmma::matrix_a, 16, 16, 16, __half, wmma::row_major> af[2];
        #pragma unroll
        for (int i = 0; i < 2; i++)
            wmma::load_matrix_sync(af[i], aSm + (mrow + i * 16) * ldS + kk, ldS);
        #pragma unroll
        for (int j = 0; j < 4; j++) {
            wmma::fragment<wmma::matrix_b, 16, 16, 16, __half, wmma::col_major> bfr;
            wmma::load_matrix_sync(bfr, bSm + (ncw + j * 16) * ldS + kk, ldS);
            #pragma unroll
            for (int i = 0; i < 2; i++)
                wmma::mma_sync(acc[i][j], af[i], bfr, acc[i][j]);
        }
    }

    // ---- epilogue: direct fp16 store (rows padded to NROWS; all tiles full) ----
    #pragma unroll
    for (int i = 0; i < 2; i++)
        #pragma unroll
        for (int j = 0; j < 4; j++)
            wmma::store_matrix_sync(C + (size_t)(row0 + mrow + i * 16) * HD + ncw + j * 16,
                                    acc[i][j], HD, wmma::mem_row_major);
}

// ---------------- Aggregation: half-warp per node, uint4 gathers ------------
__global__ __launch_bounds__(256) void k_agg(const __half* __restrict__ h,
                                             const float* __restrict__ bias,
                                             float* __restrict__ out, int n, int mode) {
    int t  = blockIdx.x * blockDim.x + threadIdx.x;
    int nd = t >> 4;              // node (half-warp)
    int hl = t & 15;              // lane within half-warp; owns 8 cols
    if (nd >= n) return;
    int start = g_rowptr[nd];
    int cnt   = g_cnt[nd];
    int c0 = hl * 8;

    float acc[8] = {0.f, 0.f, 0.f, 0.f, 0.f, 0.f, 0.f, 0.f};
    for (int e = 0; e < cnt; e++) {
        int idx  = start + e;
        int s    = g_col[idx];
        float we = g_wgt[idx];
        union { __half2 h2[4]; uint4 u; } hv;
        hv.u = *(const uint4*)(h + (size_t)s * HD + c0);
        #pragma unroll
        for (int k = 0; k < 4; k++) {
            float2 f = __half22float2(hv.h2[k]);
            acc[2 * k]     += we * f.x;
            acc[2 * k + 1] += we * f.y;
        }
    }
    float di = g_dinv[nd];
    float d2 = di * di;
    union { __half2 h2[4]; uint4 u; } hs;
    hs.u = *(const uint4*)(h + (size_t)nd * HD + c0);
    float4 bv0 = *(const float4*)&bias[c0];
    float4 bv1 = *(const float4*)&bias[c0 + 4];
    float bb[8] = {bv0.x, bv0.y, bv0.z, bv0.w, bv1.x, bv1.y, bv1.z, bv1.w};
    #pragma unroll
    for (int k = 0; k < 4; k++) {
        float2 f = __half22float2(hs.h2[k]);
        acc[2 * k]     = tanhf(acc[2 * k]     + d2 * f.x + bb[2 * k]);
        acc[2 * k + 1] = tanhf(acc[2 * k + 1] + d2 * f.y + bb[2 * k + 1]);
    }

    if (mode == 1) {
        float4 o0 = make_float4(acc[0], acc[1], acc[2], acc[3]);
        float4 o1 = make_float4(acc[4], acc[5], acc[6], acc[7]);
        *(float4*)&out[(size_t)nd * HD + c0]     = o0;
        *(float4*)&out[(size_t)nd * HD + c0 + 4] = o1;
    } else {
        union { __half2 h2[4]; uint4 u; } o;
        #pragma unroll
        for (int k = 0; k < 4; k++)
            o.h2[k] = __floats2half2_rn(acc[2 * k], acc[2 * k + 1]);
        *(uint4*)&g_ap[(size_t)nd * LDA + c0] = o.u;
    }
}

// ---------------- launch ----------------
extern "C" void kernel_launch(void* const* d_in, const int* in_sizes, int n_in,
                              void* d_out, int out_size) {
    const float* x  = (const float*)d_in[0];
    const void*  ei = d_in[1];
    const float* W0 = (const float*)d_in[2];
    const float* b0 = (const float*)d_in[3];
    const float* W1 = (const float*)d_in[4];
    const float* b1 = (const float*)d_in[5];
    const float* W2 = (const float*)d_in[6];
    const float* b2 = (const float*)d_in[7];
    const float* W3 = (const float*)d_in[8];
    const float* b3 = (const float*)d_in[9];
    float* out = (float*)d_out;

    int n  = in_sizes[0] / NF;   // 100000
    int e  = in_sizes[1] / 2;    // 1600000
    int nb = (n + 1023) / 1024;

    __half *hbuf, *apf;
    cudaGetSymbolAddress((void**)&hbuf, g_h);
    cudaGetSymbolAddress((void**)&apf, g_ap);
    const __half* ap = (const __half*)apf;

    // smem: L0 = 2*128*200*2 = 102400 ; L1-3 = 2*128*136*2 = 69632
    cudaFuncSetAttribute(k_wgemm, cudaFuncAttributeMaxDynamicSharedMemorySize, 102400);

    int ggrid = (n + 127) / 128;                // 782
    int agg_blocks = (n * 16 + 255) / 256;      // 6250

    // ---- capture fork: CSR chain on s2 runs concurrently with prep+GEMM L0 ----
    cudaStream_t s2;
    cudaStreamCreateWithFlags(&s2, cudaStreamNonBlocking);
    cudaEvent_t e1, e2;
    cudaEventCreateWithFlags(&e1, cudaEventDisableTiming);
    cudaEventCreateWithFlags(&e2, cudaEventDisableTiming);

    // root: probe + zero counters (both branches depend on this)
    k_probe_zero<<<(n + 255) / 256, 256>>>((const int*)ei, n);
    cudaEventRecord(e1, 0);
    cudaStreamWaitEvent(s2, e1, 0);

    // branch A (default stream): preps + layer-0 GEMM
    k_prep_a<<<1024, 256>>>(x, n, NF, 192, NF);
    k_prep_ball<<<288, 256>>>(W0, W1, W2, W3);
    k_wgemm<<<ggrid, 256, 102400>>>(ap, hbuf, 192, 200, B_OFF_L0);

    // branch B (s2): CSR build
    k_count<<<(e + 255) / 256, 256, 0, s2>>>(ei, e);
    k_scan1<<<nb, 1024, 0, s2>>>(n);
    k_scan2<<<1, 32, 0, s2>>>(nb);
    k_scan3<<<(n + 255) / 256, 256, 0, s2>>>(n);
    k_fill<<<(e + 255) / 256, 256, 0, s2>>>(ei, e);
    cudaEventRecord(e2, s2);
    cudaStreamWaitEvent(0, e2, 0);

    // join: layer 0 aggregate, then layers 1-3 (serial dependence)
    k_agg<<<agg_blocks, 256>>>(hbuf, b0, out, n, 0);
    k_wgemm<<<ggrid, 256, 69632>>>(ap, hbuf, HD, 136, B_OFF_L1);
    k_agg<<<agg_blocks, 256>>>(hbuf, b1, out, n, 0);
    k_wgemm<<<ggrid, 256, 69632>>>(ap, hbuf, HD, 136, B_OFF_L2);
    k_agg<<<agg_blocks, 256>>>(hbuf, b2, out, n, 0);
    k_wgemm<<<ggrid, 256, 69632>>>(ap, hbuf, HD, 136, B_OFF_L3);
    k_agg<<<agg_blocks, 256>>>(hbuf, b3, out, n, 1);
}